// round 17
// baseline (speedup 1.0000x reference)
#include <cuda_runtime.h>
#include <cuda_fp16.h>
#include <math.h>
#include <cstdint>

#define BB  64
#define NN  100
#define MM  99
#define NIN 32
#define NG  32
#define NF  64

static __device__ __forceinline__ float tanh_fast(float x) {
    float y; asm("tanh.approx.f32 %0, %1;" : "=f"(y) : "f"(x)); return y;
}
static __device__ __forceinline__ uint32_t packh2(float a, float b) {
    __half2 h = __floats2half2_rn(a, b);
    return *reinterpret_cast<uint32_t*>(&h);
}

#define MMA_F16(c, a, b0, b1v)                                                     \
    asm volatile("mma.sync.aligned.m16n8k16.row.col.f32.f16.f16.f32 "              \
        "{%0,%1,%2,%3},{%4,%5,%6,%7},{%8,%9},{%0,%1,%2,%3};"                       \
        : "+f"((c)[0]), "+f"((c)[1]), "+f"((c)[2]), "+f"((c)[3])                   \
        : "r"((a)[0]), "r"((a)[1]), "r"((a)[2]), "r"((a)[3]), "r"(b0), "r"(b1v))

__device__ float g_x[BB * NN * NF];          // x = features @ W0 (f32)
__device__ uint4 g_w1h[2 * 4 * 32];          // W1 fp16 fragment-major
__device__ uint4 g_w2h[4 * 4 * 32];          // W2 fp16 fragment-major

// ---------------------------------------------------------------------------
// Fused setup: fp16 fragment weight prep + x = features @ W0
// ---------------------------------------------------------------------------
#define W1H_N   256
#define W2H_N   512
#define SETUP_W (W1H_N + W2H_N)           // 768
__global__ void setup_kernel(const float* __restrict__ W1,
                             const float* __restrict__ W2,
                             const float* __restrict__ features,
                             const float* __restrict__ W0)
{
    int idx = blockIdx.x * blockDim.x + threadIdx.x;
    if (idx < SETUP_W) {
        const float* W = (idx < W1H_N) ? W1 : W2;
        int e = (idx < W1H_N) ? idx : idx - W1H_N;
        int lane = e & 31, blk = e >> 5;
        int ks = blk >> 2, ntp = blk & 3;
        int g = lane >> 2, t = lane & 3;
        int kb = ks * 16;
        int n0 = (2 * ntp) * 8 + g;
        int n1 = (2 * ntp + 1) * 8 + g;
        uint4 v;
        v.x = packh2(W[(kb + 2 * t) * NF + n0],     W[(kb + 2 * t + 1) * NF + n0]);
        v.y = packh2(W[(kb + 2 * t + 8) * NF + n0], W[(kb + 2 * t + 9) * NF + n0]);
        v.z = packh2(W[(kb + 2 * t) * NF + n1],     W[(kb + 2 * t + 1) * NF + n1]);
        v.w = packh2(W[(kb + 2 * t + 8) * NF + n1], W[(kb + 2 * t + 9) * NF + n1]);
        if (idx < W1H_N) g_w1h[e] = v; else g_w2h[e] = v;
        return;
    }
    int ix = idx - SETUP_W;
    if (ix >= BB * NN * NF) return;
    int f   = ix & (NF - 1);
    int row = ix >> 6;
    const float* feat = features + row * NIN;
    float acc = 0.f;
#pragma unroll
    for (int k = 0; k < NIN; k++)
        acc = fmaf(feat[k], W0[k * NF + f], acc);
    g_x[ix] = acc;
}

// ---------------------------------------------------------------------------
// One CTA per 2 atoms. 256 threads: warps 0-3 atom0, 4-7 atom1.
// Warp-local 16-row chunks. A-fragments loaded DIRECTLY from global (no smem
// slab, no syncwarp in mainloop). b1 folded into GEMM1 acc init (f32 tanh at
// zero add cost); b2 folded into GEMM2 acc init. tanh feeds GEMM2 A-regs.
// ---------------------------------------------------------------------------
__global__ __launch_bounds__(256, 3)
void interaction_kernel(const float* __restrict__ rbf,
                        const int*   __restrict__ nbr_list,
                        const float* __restrict__ b1,
                        const float* __restrict__ b2,
                        const float* __restrict__ nbrf,
                        const float* __restrict__ W3, const float* __restrict__ b3,
                        const float* __restrict__ W4, const float* __restrict__ b4,
                        float* __restrict__ out,
                        float* __restrict__ attn)
{
    __shared__ uint4 sB1h[W1H_N];
    __shared__ uint4 sB2h[W2H_N];
    __shared__ int   sNL[200];
    __shared__ float sB2V[NF];
    __shared__ float sNF[NF];
    __shared__ float sLG[200];
    __shared__ float sMG[2 * 4 * 4 * 18];
    __shared__ float sVC[128];
    __shared__ float sFN[4];
    __shared__ float sHD[128];

    const int tid  = threadIdx.x;
    const int wid  = tid >> 5;
    const int lane = tid & 31;
    const int g    = lane >> 2;
    const int t    = lane & 3;
    const int a    = wid >> 2;            // atom within CTA
    const int wt   = wid & 3;             // warp within atom group
    const int bn0  = blockIdx.x * 2;
    const int b    = bn0 / NN;

    // ---- cooperative stage (one barrier) ----
    for (int idx = tid; idx < W1H_N; idx += 256) sB1h[idx] = g_w1h[idx];
    for (int idx = tid; idx < W2H_N; idx += 256) sB2h[idx] = g_w2h[idx];
    if (tid < 200) {
        int aa = tid / 100, m = tid % 100;
        sNL[tid] = (m < MM) ? nbr_list[(bn0 + aa) * MM + m] : 0;
    }
    if (tid < NF) {
        sB2V[tid] = b2[tid];
        sNF[tid]  = nbrf[tid];
    }
    __syncthreads();

    // b1 column pairs for this thread (same for both acc rows), from global
    float2 bv1[8];
#pragma unroll
    for (int nt = 0; nt < 8; nt++)
        bv1[nt] = *(const float2*)(b1 + 8 * nt + 2 * t);

    const float* rbf_a = rbf + (size_t)(bn0 + a) * MM * NG;
    const float* gx_b  = g_x + b * (NN * NF);
    const int*   nlA   = sNL + a * 100;
    float*       lgA   = sLG + a * 100;

    float m_run = -1e30f, d_run = 0.f;
    float agg[16];
#pragma unroll
    for (int i = 0; i < 16; i++) agg[i] = 0.f;

#pragma unroll
    for (int mt = 0; mt < 2; mt++) {
        const int rowbase = wt * 32 + mt * 16;
        const int r0 = rowbase + g;
        const int r1 = r0 + 8;
        const bool v0 = r0 < MM, v1 = r1 < MM;
        // clamped source rows (garbage rows are row-local and discarded)
        const float* p0 = rbf_a + (size_t)(v0 ? r0 : 0) * NG;
        const float* p1 = rbf_a + (size_t)(v1 ? r1 : 0) * NG;

        // ---- GEMM1 A-fragments straight from global ----
        uint32_t af[2][4];
#pragma unroll
        for (int ks = 0; ks < 2; ks++) {
            float2 v00 = *(const float2*)(p0 + 16 * ks + 2 * t);
            float2 v10 = *(const float2*)(p1 + 16 * ks + 2 * t);
            float2 v01 = *(const float2*)(p0 + 16 * ks + 8 + 2 * t);
            float2 v11 = *(const float2*)(p1 + 16 * ks + 8 + 2 * t);
            af[ks][0] = packh2(v00.x, v00.y);
            af[ks][1] = packh2(v10.x, v10.y);
            af[ks][2] = packh2(v01.x, v01.y);
            af[ks][3] = packh2(v11.x, v11.y);
        }

        // ---- GEMM1: acc init = b1 (bias folded) ----
        float acc[8][4];
#pragma unroll
        for (int nt = 0; nt < 8; nt++) {
            acc[nt][0] = bv1[nt].x; acc[nt][1] = bv1[nt].y;
            acc[nt][2] = bv1[nt].x; acc[nt][3] = bv1[nt].y;
        }
#pragma unroll
        for (int ks = 0; ks < 2; ks++)
#pragma unroll
            for (int ntp = 0; ntp < 4; ntp++) {
                uint4 bb = sB1h[(ks * 4 + ntp) * 32 + lane];
                MMA_F16(acc[2 * ntp],     af[ks], bb.x, bb.y);
                MMA_F16(acc[2 * ntp + 1], af[ks], bb.z, bb.w);
            }

        // ---- f32 tanh -> GEMM2 A-fragments in registers ----
        uint32_t ah[4][4];
#pragma unroll
        for (int ks = 0; ks < 4; ks++) {
            ah[ks][0] = packh2(tanh_fast(acc[2 * ks][0]),     tanh_fast(acc[2 * ks][1]));
            ah[ks][1] = packh2(tanh_fast(acc[2 * ks][2]),     tanh_fast(acc[2 * ks][3]));
            ah[ks][2] = packh2(tanh_fast(acc[2 * ks + 1][0]), tanh_fast(acc[2 * ks + 1][1]));
            ah[ks][3] = packh2(tanh_fast(acc[2 * ks + 1][2]), tanh_fast(acc[2 * ks + 1][3]));
        }

        // ---- GEMM2: acc init = b2 (bias folded) ----
#pragma unroll
        for (int nt = 0; nt < 8; nt++) {
            float2 bb = *(const float2*)(sB2V + 8 * nt + 2 * t);
            acc[nt][0] = bb.x; acc[nt][1] = bb.y;
            acc[nt][2] = bb.x; acc[nt][3] = bb.y;
        }
#pragma unroll
        for (int ks = 0; ks < 4; ks++)
#pragma unroll
            for (int ntp = 0; ntp < 4; ntp++) {
                uint4 bb = sB2h[(ks * 4 + ntp) * 32 + lane];
                MMA_F16(acc[2 * ntp],     ah[ks], bb.x, bb.y);
                MMA_F16(acc[2 * ntp + 1], ah[ks], bb.z, bb.w);
            }

        // ---- epilogue for this chunk's 2 rows per lane ----
        {
            int nb0 = v0 ? nlA[r0] : 0;
            int nb1 = v1 ? nlA[r1] : 0;
            const float* x0p = gx_b + nb0 * NF;
            const float* x1p = gx_b + nb1 * NF;
            float p0l = 0.f, p1l = 0.f;
#pragma unroll
            for (int nt = 0; nt < 8; nt++) {
                int c = 8 * nt + 2 * t;
                float2 x0 = *(const float2*)(x0p + c);
                float2 x1 = *(const float2*)(x1p + c);
                float2 nf = *(const float2*)(sNF + c);
                float cf00 = x0.x * acc[nt][0];
                float cf01 = x0.y * acc[nt][1];
                float cf10 = x1.x * acc[nt][2];
                float cf11 = x1.y * acc[nt][3];
                acc[nt][0] = cf00; acc[nt][1] = cf01;
                acc[nt][2] = cf10; acc[nt][3] = cf11;
                p0l += cf00 * nf.x + cf01 * nf.y;
                p1l += cf10 * nf.x + cf11 * nf.y;
            }
            p0l += __shfl_xor_sync(0xffffffffu, p0l, 1);
            p0l += __shfl_xor_sync(0xffffffffu, p0l, 2);
            p1l += __shfl_xor_sync(0xffffffffu, p1l, 1);
            p1l += __shfl_xor_sync(0xffffffffu, p1l, 2);
            if (v0 && t == 0) lgA[r0] = p0l;
            if (v1 && t == 0) lgA[r1] = p1l;

            if (v0) {
                float mn = fmaxf(m_run, p0l);
                float s  = __expf(m_run - mn);
                float e  = __expf(p0l - mn);
                d_run = d_run * s + e;
#pragma unroll
                for (int nt = 0; nt < 8; nt++) {
                    agg[2 * nt]     = agg[2 * nt]     * s + e * acc[nt][0];
                    agg[2 * nt + 1] = agg[2 * nt + 1] * s + e * acc[nt][1];
                }
                m_run = mn;
            }
            if (v1) {
                float mn = fmaxf(m_run, p1l);
                float s  = __expf(m_run - mn);
                float e  = __expf(p1l - mn);
                d_run = d_run * s + e;
#pragma unroll
                for (int nt = 0; nt < 8; nt++) {
                    agg[2 * nt]     = agg[2 * nt]     * s + e * acc[nt][2];
                    agg[2 * nt + 1] = agg[2 * nt + 1] * s + e * acc[nt][3];
                }
                m_run = mn;
            }
        }
    }

    // ---- in-warp butterfly merge across row groups ----
#pragma unroll
    for (int off = 4; off <= 16; off <<= 1) {
        float m2 = __shfl_xor_sync(0xffffffffu, m_run, off);
        float d2 = __shfl_xor_sync(0xffffffffu, d_run, off);
        float mn = fmaxf(m_run, m2);
        float s1 = __expf(m_run - mn);
        float s2 = __expf(m2 - mn);
        d_run = d_run * s1 + d2 * s2;
#pragma unroll
        for (int i = 0; i < 16; i++) {
            float a2 = __shfl_xor_sync(0xffffffffu, agg[i], off);
            agg[i] = agg[i] * s1 + a2 * s2;
        }
        m_run = mn;
    }

    // ---- cross-warp merge via smem ----
    if (lane < 4) {
        float* dst = sMG + (((a * 4 + wt) * 4) + lane) * 18;
        dst[0] = m_run; dst[1] = d_run;
#pragma unroll
        for (int i = 0; i < 16; i++) dst[2 + i] = agg[i];
    }
    __syncthreads();

    if (tid < 8) {
        int aa = tid >> 2, tt4 = tid & 3;
        const float* s0 = sMG + ((aa * 4 + 0) * 4 + tt4) * 18;
        float mf = s0[0], df = s0[1], ag[16];
#pragma unroll
        for (int i = 0; i < 16; i++) ag[i] = s0[2 + i];
#pragma unroll
        for (int w = 1; w < 4; w++) {
            const float* sw = sMG + ((aa * 4 + w) * 4 + tt4) * 18;
            float m2 = sw[0], d2 = sw[1];
            float mn = fmaxf(mf, m2);
            float s1 = __expf(mf - mn);
            float s2 = __expf(m2 - mn);
            df = df * s1 + d2 * s2;
#pragma unroll
            for (int i = 0; i < 16; i++) ag[i] = ag[i] * s1 + sw[2 + i] * s2;
            mf = mn;
        }
        float inv = 1.f / df;
#pragma unroll
        for (int nt = 0; nt < 8; nt++) {
            int c = 8 * nt + 2 * tt4;
            sVC[aa * 64 + c]     = ag[2 * nt] * inv;
            sVC[aa * 64 + c + 1] = ag[2 * nt + 1] * inv;
        }
        if (tt4 == 0) { sFN[2 * aa] = mf; sFN[2 * aa + 1] = df; }
    }
    __syncthreads();

    // ---- attn outputs ----
    {
        int aa  = tid >> 7;
        int ltd = tid & 127;
        if (ltd < MM)
            attn[(bn0 + aa) * MM + ltd] =
                __expf(sLG[aa * 100 + ltd] - sFN[2 * aa]) / sFN[2 * aa + 1];
    }

    // ---- output MLP, k-split across lane quads ----
    {
        const int j = tid >> 2;
        const int s = tid & 3;
        float t0 = 0.f, t1 = 0.f;
#pragma unroll
        for (int i = 0; i < 16; i++) {
            int k = 4 * i + s;
            float w = __ldg(W3 + k * NF + j);
            t0 = fmaf(sVC[k],      w, t0);
            t1 = fmaf(sVC[64 + k], w, t1);
        }
        t0 += __shfl_xor_sync(0xffffffffu, t0, 1);
        t0 += __shfl_xor_sync(0xffffffffu, t0, 2);
        t1 += __shfl_xor_sync(0xffffffffu, t1, 1);
        t1 += __shfl_xor_sync(0xffffffffu, t1, 2);
        if (s == 0) {
            float bj = __ldg(b3 + j);
            sHD[j]      = tanh_fast(t0 + bj);
            sHD[64 + j] = tanh_fast(t1 + bj);
        }
    }
    __syncthreads();
    {
        const int j = tid >> 2;
        const int s = tid & 3;
        float o0 = 0.f, o1 = 0.f;
#pragma unroll
        for (int i = 0; i < 16; i++) {
            int k = 4 * i + s;
            float w = __ldg(W4 + k * NF + j);
            o0 = fmaf(sHD[k],      w, o0);
            o1 = fmaf(sHD[64 + k], w, o1);
        }
        o0 += __shfl_xor_sync(0xffffffffu, o0, 1);
        o0 += __shfl_xor_sync(0xffffffffu, o0, 2);
        o1 += __shfl_xor_sync(0xffffffffu, o1, 1);
        o1 += __shfl_xor_sync(0xffffffffu, o1, 2);
        if (s == 0) {
            float bj = __ldg(b4 + j);
            out[bn0 * NF + j]       = o0 + bj;
            out[(bn0 + 1) * NF + j] = o1 + bj;
        }
    }
}

// ---------------------------------------------------------------------------
extern "C" void kernel_launch(void* const* d_in, const int* in_sizes, int n_in,
                              void* d_out, int out_size)
{
    const float* features = (const float*)d_in[0];
    const float* rbf      = (const float*)d_in[1];
    const int*   nbr      = (const int*)  d_in[2];
    const float* W0       = (const float*)d_in[3];
    const float* W1       = (const float*)d_in[4];
    const float* b1       = (const float*)d_in[5];
    const float* W2       = (const float*)d_in[6];
    const float* b2       = (const float*)d_in[7];
    const float* nbrf     = (const float*)d_in[8];
    const float* W3       = (const float*)d_in[9];
    const float* b3       = (const float*)d_in[10];
    const float* W4       = (const float*)d_in[11];
    const float* b4       = (const float*)d_in[12];

    float* out  = (float*)d_out;                 // [B, N, NF]
    float* attn = out + BB * NN * NF;            // [B, N, M]

    const int setup_elems = SETUP_W + BB * NN * NF;
    setup_kernel<<<(setup_elems + 255) / 256, 256>>>(W1, W2, features, W0);
    interaction_kernel<<<BB * NN / 2, 256>>>(rbf, nbr, b1, b2, nbrf,
                                             W3, b3, W4, b4, out, attn);
}